// round 10
// baseline (speedup 1.0000x reference)
#include <cuda_runtime.h>

// NPZD Euler: 1024*52 independent 168-step chains.
// t_idx[w,j] = 168*w + j exactly -> f/delta are contiguous 168-float windows.
//
// Round-10 = Round-9 resubmitted (R9 bench died to the recurring container
// bring-up infra failure also seen in R0/R4/R5; R4/R5's source passed
// unchanged in R6). Changes vs best-passing R8 (24.5us, issue 60.2%):
//  * packed f32x2 math: 2 chains per thread, the whole 4-state FMA tree runs
//    as add/mul/fma.rn.f32x2 -> total FP instruction count ~1.55x lower.
//    MUFU rcp/ex2 and fmax stay scalar per half. Coefficients are per-thread
//    packed (coefA, coefB) so the chain pair need not share a batch.
//  * 832 blocks x 32 threads (64 chains/block). SMEM chunk layout: float4
//    (fA, fB, dA, dB) per step, pitch 13 float4 -> conflict-free LDS.128
//    whose (x,y)/(z,w) halves land as aligned packed-register pairs.
//  * 12-step sub-chunks keep register-staged prefetch at 48 regs; output
//    sample every 2nd sub-chunk at compile time; coalesced SMEM-staged
//    epilogue kept from R8.

#define BB 1024
#define WW 52
#define HOURS 8760
#define TSTEPS 168
#define TPB 32
#define SUB 12
#define NSC 7                  // 7 super-chunks x 2 sub-chunks x 12 = 168
#define P4 13                  // float4 pitch (odd) -> conflict-free LDS.128
#define OPITCH 33              // output staging pitch -> conflict-free

typedef unsigned long long ull;

__device__ __forceinline__ float ex2_approx(float x) {
    float r; asm("ex2.approx.f32 %0, %1;" : "=f"(r) : "f"(x)); return r;
}
__device__ __forceinline__ float rcp_approx(float x) {
    float r; asm("rcp.approx.f32 %0, %1;" : "=f"(r) : "f"(x)); return r;
}
__device__ __forceinline__ ull pk(float a, float b) {
    ull r; asm("mov.b64 %0, {%1, %2};" : "=l"(r) : "f"(a), "f"(b)); return r;
}
__device__ __forceinline__ void upk(ull v, float& a, float& b) {
    asm("mov.b64 {%0, %1}, %2;" : "=f"(a), "=f"(b) : "l"(v));
}
__device__ __forceinline__ ull add2(ull a, ull b) {
    ull r; asm("add.rn.f32x2 %0, %1, %2;" : "=l"(r) : "l"(a), "l"(b)); return r;
}
__device__ __forceinline__ ull mul2(ull a, ull b) {
    ull r; asm("mul.rn.f32x2 %0, %1, %2;" : "=l"(r) : "l"(a), "l"(b)); return r;
}
__device__ __forceinline__ ull fma2(ull a, ull b, ull c) {
    ull r; asm("fma.rn.f32x2 %0, %1, %2, %3;" : "=l"(r) : "l"(a), "l"(b), "l"(c)); return r;
}

__global__ __launch_bounds__(TPB, 6) void npzd_kernel(
    const float* __restrict__ X_in,      // (B, W, 5, 1)
    const float* __restrict__ gf,        // (B, HOURS)
    const float* __restrict__ gd,        // (B, HOURS)
    const float* __restrict__ params,    // (B, 10)
    float* __restrict__ out)             // (B, W, 4, 8)
{
    __shared__ float4 ism4[TPB * P4];    // per step: (fA, fB, dA, dB) * dt
    __shared__ float  osm[64 * OPITCH];  // 64 output records staging
    __shared__ int    bases_s[64];

    const int t = threadIdx.x;           // lane
    const int pA = blockIdx.x * 64 + t;       // chain A
    const int pB = pA + 32;                   // chain B
    const int bA = pA / WW, wA = pA - bA * WW;
    const int bB = pB / WW, wB = pB - bB * WW;

    bases_s[t]      = bA * HOURS + wA * TSTEPS;   // multiples of 8 floats
    bases_s[t + 32] = bB * HOURS + wB * TSTEPS;

    const float dt  = 1.0f / 24.0f;
    const float thr = 0.01f;

    const float* ppA = params + bA * 10;
    const float* ppB = params + bB * 10;

    // packed per-thread coefficients (chain A in .x, chain B in .y)
    #define PCOEF(i, s) pk(ppA[i] * (s), ppB[i] * (s))
    const ull Kn2    = PCOEF(0, 1.0f);
    const ull Rm2    = PCOEF(1, 2.0f);
    const ull dtg2   = PCOEF(2, 0.1f  * dt);
    const ull nl2    = PCOEF(3, -0.05f * 1.44269504f);  // -lam*log2e
    const ull dta2   = PCOEF(5, 0.3f  * dt);
    const ull dte2   = PCOEF(4, 0.1f  * dt);
    const ull dtphi2 = PCOEF(8, 0.4f  * dt);
    const ull dtb2   = PCOEF(6, 0.6f  * dt);
    const ull dtr2   = PCOEF(7, 0.15f * dt);
    const ull dtab2  = pk(dt * (1.0f - ppA[5]*0.3f - ppA[6]*0.6f),
                          dt * (1.0f - ppB[5]*0.3f - ppB[6]*0.6f));
    const ull cpn2   = pk(-dt * (ppA[4]*0.1f + ppA[7]*0.15f),
                          -dt * (ppB[4]*0.1f + ppB[7]*0.15f));  // -(eps+r)dt
    const ull cdn2   = pk(-dt * (ppA[8]*0.4f + ppA[9]*0.1f),
                          -dt * (ppB[8]*0.4f + ppB[9]*0.1f));   // -(phi+Sw)dt
    const ull dtgn2  = pk(-dt * ppA[2]*0.1f, -dt * ppB[2]*0.1f);
    #undef PCOEF
    const ull m1_2    = pk(-1.0f, -1.0f);
    const ull one2    = pk(1.0f, 1.0f);
    const ull eight2  = pk(8.0f, 8.0f);      // Q0 = 8
    const ull dtn2    = pk(-dt, -dt);

    // initial states (packed)
    const float* xA = X_in + (size_t)pA * 5;
    const float* xB = X_in + (size_t)pB * 5;
    ull N = pk(xA[1], xB[1]);
    ull P = pk(xA[2], xB[2]);
    ull Z = pk(xA[3], xB[3]);
    ull D = pk(xA[4], xB[4]);

    // sample 0 into staging
    {
        float a, b2;
        upk(N, a, b2); osm[t*OPITCH + 0]  = a; osm[(t+32)*OPITCH + 0]  = b2;
        upk(P, a, b2); osm[t*OPITCH + 8]  = a; osm[(t+32)*OPITCH + 8]  = b2;
        upk(Z, a, b2); osm[t*OPITCH + 16] = a; osm[(t+32)*OPITCH + 16] = b2;
        upk(D, a, b2); osm[t*OPITCH + 24] = a; osm[(t+32)*OPITCH + 24] = b2;
    }

    // initial gam / mP / zoo (packed, MUFU per half)
    ull gam, mP, zoo;
    {
        float ka, kb, pa, pb, za, zb, ea, eb;
        upk(add2(Kn2, N), ka, kb);
        gam = mul2(N, pk(rcp_approx(ka), rcp_approx(kb)));
        upk(P, pa, pb);
        mP = pk(fmaxf(thr, pa), fmaxf(thr, pb));
        upk(Z, za, zb);
        ull RmZ = mul2(Rm2, pk(fmaxf(thr, za), fmaxf(thr, zb)));
        upk(mul2(nl2, mP), ea, eb);
        ull ex = pk(ex2_approx(ea), ex2_approx(eb));
        zoo = mul2(RmZ, fma2(ex, m1_2, one2));
    }

    const int fb4 = t * P4;
    __syncwarp();                            // bases_s visible

    // register staging: warp-cooperative slice of one 12-step sub-chunk
    // (64 rows x 3 float4 per array = 192 float4 per array -> 6/thread each)
    float4 fr[6], dr[6];

    auto load_sub = [&](int s) {
        const int cb = s * SUB;
        #pragma unroll
        for (int q = 0; q < 6; ++q) {
            int i   = q * TPB + t;           // 0..191
            int row = i / 3;                 // 3 float4 per row
            int e   = i - row * 3;
            int g   = bases_s[row] + cb + e * 4;
            fr[q] = *reinterpret_cast<const float4*>(gf + g);
            dr[q] = *reinterpret_cast<const float4*>(gd + g);
        }
    };

    auto sts_sub = [&]() {
        float* isf = reinterpret_cast<float*>(ism4);
        #pragma unroll
        for (int q = 0; q < 6; ++q) {
            int i   = q * TPB + t;
            int row = i / 3;
            int e   = i - row * 3;
            int rr2 = row & 31;
            int sel = (row < 32) ? 0 : 1;    // .x/.y for f, .z/.w for d
            int base = rr2 * (P4 * 4) + e * 16 + sel;
            const float* fv = &fr[q].x;
            const float* dv = &dr[q].x;
            #pragma unroll
            for (int kk = 0; kk < 4; ++kk) {
                isf[base + kk * 4]     = dt * fv[kk];
                isf[base + kk * 4 + 2] = dt * dv[kk];
            }
        }
    };

    auto compute_sub = [&]() {
        #pragma unroll
        for (int jj = 0; jj < SUB; ++jj) {
            const float4 v = ism4[fb4 + jj];
            const ull fp = pk(v.x, v.y);     // dt*f   (A, B)
            const ull dd = pk(v.z, v.w);     // dt*dlt (A, B)

            const ull ddn  = mul2(dd, m1_2);
            const ull cpdn = add2(ddn, cpn2);
            const ull gddn = add2(ddn, dtgn2);
            const ull cddn = add2(ddn, cdn2);

            const ull dtup = mul2(mul2(gam, fp), mP);   // Vm=1, dt in fp

            const ull t1 = fma2(dta2, zoo, mul2(dte2, P));
            const ull t2 = fma2(dtg2, Z, mul2(dtphi2, D));
            const ull t3 = mul2(eight2, dd);
            const ull t4 = fma2(ddn, N, N);
            const ull s  = add2(add2(t1, t2), add2(t3, t4));
            const ull N1 = fma2(dtup, m1_2, s);

            const ull q1 = fma2(cpdn, P, P);
            const ull q2 = fma2(dtn2, zoo, dtup);
            const ull P1 = add2(q1, q2);

            const ull Z1 = fma2(dtb2, zoo, fma2(gddn, Z, Z));

            const ull u1 = fma2(cddn, D, D);
            const ull u2 = fma2(dtr2, P, mul2(dtab2, zoo));
            const ull D1 = add2(u1, u2);

            N = N1; P = P1; Z = Z1; D = D1;

            float ka, kb, pa, pb, za, zb, ea, eb;
            upk(add2(Kn2, N1), ka, kb);
            gam = mul2(N1, pk(rcp_approx(ka), rcp_approx(kb)));
            upk(P1, pa, pb);
            mP = pk(fmaxf(thr, pa), fmaxf(thr, pb));
            upk(Z1, za, zb);
            const ull RmZ = mul2(Rm2, pk(fmaxf(thr, za), fmaxf(thr, zb)));
            upk(mul2(nl2, mP), ea, eb);
            const ull ex = pk(ex2_approx(ea), ex2_approx(eb));
            zoo = mul2(RmZ, fma2(ex, m1_2, one2));
        }
    };

    load_sub(0);                             // prefetch sub-chunk 0

    #pragma unroll 1
    for (int sc = 0; sc < NSC; ++sc) {
        // ---- sub-chunk 2*sc ----
        sts_sub();
        __syncwarp();
        load_sub(2 * sc + 1);                // prefetch next (always valid)
        compute_sub();
        __syncwarp();

        // ---- sub-chunk 2*sc+1 ----
        sts_sub();
        __syncwarp();
        if (sc < NSC - 1) load_sub(2 * sc + 2);
        compute_sub();
        __syncwarp();

        // one output sample per 24 steps, compile-time position
        const int k = sc + 1;
        float a, b2;
        upk(N, a, b2); osm[t*OPITCH + k]      = a; osm[(t+32)*OPITCH + k]      = b2;
        upk(P, a, b2); osm[t*OPITCH + 8 + k]  = a; osm[(t+32)*OPITCH + 8 + k]  = b2;
        upk(Z, a, b2); osm[t*OPITCH + 16 + k] = a; osm[(t+32)*OPITCH + 16 + k] = b2;
        upk(D, a, b2); osm[t*OPITCH + 24 + k] = a; osm[(t+32)*OPITCH + 24 + k] = b2;
    }

    // epilogue: coalesced output. Block owns out[blockIdx*2048 .. +2048).
    __syncwarp();
    float* obase = out + (size_t)blockIdx.x * (64 * 32);
    #pragma unroll
    for (int s = 0; s < 64; ++s) {
        obase[s * 32 + t] = osm[s * OPITCH + t];   // conflict-free
    }
}

extern "C" void kernel_launch(void* const* d_in, const int* in_sizes, int n_in,
                              void* d_out, int out_size) {
    const float* X_in  = (const float*)d_in[0];
    const float* gf    = (const float*)d_in[1];
    const float* gd    = (const float*)d_in[2];
    const float* par   = (const float*)d_in[3];
    float* out = (float*)d_out;

    npzd_kernel<<<(BB * WW) / 64, TPB>>>(X_in, gf, gd, par, out);
}

// round 11
// speedup vs baseline: 1.5301x; 1.5301x over previous
#include <cuda_runtime.h>

// NPZD Euler: 1024*52 independent 168-step chains.
// t_idx[w,j] = 168*w + j exactly -> f/delta are contiguous 168-float windows.
//
// Round-11 (best = R8 24.5us, issue 60.2%; R10 packed-f32x2 regressed by
// halving warps -> warp count is sacred). R8 skeleton + overhead cuts:
//  * SMEM holds step-pairs (f_j, d_j, f_j+1, d_j+1) as float4, pitch 13
//    -> one conflict-free LDS.128 per 2 steps (was LDS.64 per step).
//  * fill uses STS.128 (12/chunk instead of 24 STS.64).
//  * no shfl / bases SMEM: 6 per-thread row-base offsets precomputed once.
//  * decay terms as nested FFMAs -> inner op independent of the LDS value,
//    issues under the LDS shadow.
//  * keeps: TPB=32 x 1664 blocks (max warps), register-staged prefetch,
//    CHUNK=24 branchless sampling, (dt*f, dt*delta) folding at STS time,
//    staged coalesced epilogue, raw ex2/rcp approx.

#define BB 1024
#define WW 52
#define HOURS 8760
#define TSTEPS 168
#define TPB 32
#define CHUNK 24
#define NCHUNK 7               // 7 * 24 = 168
#define P4 13                  // float4 pitch (12 pairs + 1 pad) conflict-free
#define OPITCH 33              // output staging pitch -> conflict-free

__device__ __forceinline__ float ex2_approx(float x) {
    float r; asm("ex2.approx.f32 %0, %1;" : "=f"(r) : "f"(x)); return r;
}
__device__ __forceinline__ float rcp_approx(float x) {
    float r; asm("rcp.approx.f32 %0, %1;" : "=f"(r) : "f"(x)); return r;
}

__global__ __launch_bounds__(TPB, 12) void npzd_kernel(
    const float* __restrict__ X_in,      // (B, W, 5, 1)
    const float* __restrict__ gf,        // (B, HOURS)
    const float* __restrict__ gd,        // (B, HOURS)
    const float* __restrict__ params,    // (B, 10)
    float* __restrict__ out)             // (B, W, 4, 8)
{
    __shared__ float4 ism4[TPB * P4];    // 12 step-pair float4 per chain row
    __shared__ float  osm[TPB * OPITCH]; // output record staging

    const int t = threadIdx.x;           // lane
    const int p = blockIdx.x * TPB + t;  // this thread's chain
    const int b = p / WW;
    const int w = p - b * WW;

    const float dt  = 1.0f / 24.0f;
    const float thr = 0.01f;

    const float* pp = params + b * 10;
    const float Kn    = pp[0] * 1.0f;
    const float Rm    = pp[1] * 2.0f;
    const float gz    = pp[2] * 0.1f;
    const float lam   = pp[3] * 0.05f;
    const float eps   = pp[4] * 0.1f;
    const float alpha = pp[5] * 0.3f;
    const float beta  = pp[6] * 0.6f;
    const float rr    = pp[7] * 0.15f;
    const float phi   = pp[8] * 0.4f;
    const float Sw    = pp[9] * 0.1f;

    const float dta   = dt * alpha;
    const float dte   = dt * eps;
    const float dtg   = dt * gz;
    const float dtphi = dt * phi;
    const float dtb   = dt * beta;
    const float dtr   = dt * rr;
    const float dtab  = dt * (1.0f - alpha - beta);
    const float cp    = dt * (eps + rr);       // (eps + r)*dt
    const float cd    = dt * (phi + Sw);       // (phi + Sw)*dt
    const float nl    = -lam * 1.44269504f;    // fold log2(e) into lambda

    const float* xi = X_in + (size_t)p * 5;
    float N = xi[1];
    float P = xi[2];
    float Z = xi[3];
    float D = xi[4];

    // sample 0 into staging (record layout: [state*8 + k], k=0..7)
    const int ob = t * OPITCH;
    osm[ob + 0]  = N;
    osm[ob + 8]  = P;
    osm[ob + 16] = Z;
    osm[ob + 24] = D;

    float gam = N * rcp_approx(Kn + N);
    float mP  = fmaxf(thr, P);
    float zoo;
    {
        float RmZ = Rm * fmaxf(thr, Z);
        zoo = fmaf(-RmZ, ex2_approx(nl * mP), RmZ);
    }

    // per-thread cooperative-load assignment: 6 slices i = q*32+t,
    // row = i/6 (chain in block), e = i%6 (float4 within 24-float chunk).
    // gbase[q] = global float index of that slice at chunk 0.
    int  gbase[6];
    int  soff[6];                        // SMEM float4 offset (pair index base)
    #pragma unroll
    for (int q = 0; q < 6; ++q) {
        int i    = q * TPB + t;          // 0..191
        int row  = i / 6;
        int e    = i - row * 6;
        int prow = blockIdx.x * TPB + row;
        int br   = prow / WW;
        int wr   = prow - br * WW;
        gbase[q] = br * HOURS + wr * TSTEPS + e * 4;  // 16B-aligned
        soff[q]  = row * P4 + e * 2;     // two float4 pairs per slice
    }

    const int fb4 = t * P4;

    // register staging for the next chunk (warp-cooperative, 48 floats)
    float4 fr[6], dr[6];

    // prefetch chunk 0
    #pragma unroll
    for (int q = 0; q < 6; ++q) {
        fr[q] = *reinterpret_cast<const float4*>(gf + gbase[q]);
        dr[q] = *reinterpret_cast<const float4*>(gd + gbase[q]);
    }

    #pragma unroll 1
    for (int c = 0; c < NCHUNK; ++c) {
        // STS.128: step-pair interleave, dt folded into both f and delta
        #pragma unroll
        for (int q = 0; q < 6; ++q) {
            ism4[soff[q]]     = make_float4(dt * fr[q].x, dt * dr[q].x,
                                            dt * fr[q].y, dt * dr[q].y);
            ism4[soff[q] + 1] = make_float4(dt * fr[q].z, dt * dr[q].z,
                                            dt * fr[q].w, dt * dr[q].w);
        }
        __syncwarp();                    // chunk c visible warp-wide

        // prefetch chunk c+1 while computing chunk c (DRAM latency hidden)
        if (c < NCHUNK - 1) {
            const int cbase = (c + 1) * CHUNK;
            #pragma unroll
            for (int q = 0; q < 6; ++q) {
                fr[q] = *reinterpret_cast<const float4*>(gf + gbase[q] + cbase);
                dr[q] = *reinterpret_cast<const float4*>(gd + gbase[q] + cbase);
            }
        }

        #pragma unroll
        for (int jj = 0; jj < CHUNK / 2; ++jj) {
            const float4 v = ism4[fb4 + jj];   // (f0,d0,f1,d1), dt-scaled
            #pragma unroll
            for (int h = 0; h < 2; ++h) {
                const float fp = h ? v.z : v.x;     // dt*f
                const float dd = h ? v.w : v.y;     // dt*delta

                const float dtup = (gam * fp) * mP;      // Vm=1, dt in fp

                // N1 = N(1-dd) + dta*zoo + dte*P + dtg*Z + dtphi*D + 8dd - dtup
                const float t1 = fmaf(dta, zoo, dte * P);
                const float t2 = fmaf(dtg, Z, dtphi * D);
                const float t3 = fmaf(8.0f, dd, -dtup);  // Q0 = 8
                const float t4 = fmaf(-dd, N, N);
                const float N1 = (t1 + t2) + (t3 + t4);

                // P1 = P(1 - cp - dd) + dtup - dt*zoo   (nested FFMA decay)
                const float p0 = fmaf(-cp, P, P);        // independent of dd
                const float P1 = fmaf(-dd, P, p0) + fmaf(-dt, zoo, dtup);

                // Z1 = Z(1 - dtg - dd) + dtb*zoo
                const float z0 = fmaf(-dtg, Z, Z);
                const float Z1 = fmaf(dtb, zoo, fmaf(-dd, Z, z0));

                // D1 = D(1 - cd - dd) + dtr*P + dtab*zoo
                const float d0 = fmaf(-cd, D, D);
                const float D1 = fmaf(-dd, D, d0) + fmaf(dtr, P, dtab * zoo);

                N = N1; P = P1; Z = Z1; D = D1;

                gam = N1 * rcp_approx(Kn + N1);
                mP  = fmaxf(thr, P1);
                const float RmZ = Rm * fmaxf(thr, Z1);
                zoo = fmaf(-RmZ, ex2_approx(nl * mP), RmZ);
            }
        }

        // one output sample per 24-step chunk -> SMEM staging (conflict-free)
        const int k = c + 1;
        osm[ob + k]      = N;
        osm[ob + 8 + k]  = P;
        osm[ob + 16 + k] = Z;
        osm[ob + 24 + k] = D;

        __syncwarp();                    // all reads of ism4 done
    }

    // epilogue: coalesced output. Block owns out[blockIdx*1024 .. +1024).
    __syncwarp();
    float* obase = out + (size_t)blockIdx.x * (TPB * 32);
    #pragma unroll
    for (int s = 0; s < 32; ++s) {
        obase[s * 32 + t] = osm[s * OPITCH + t];   // conflict-free
    }
}

extern "C" void kernel_launch(void* const* d_in, const int* in_sizes, int n_in,
                              void* d_out, int out_size) {
    const float* X_in  = (const float*)d_in[0];
    const float* gf    = (const float*)d_in[1];
    const float* gd    = (const float*)d_in[2];
    const float* par   = (const float*)d_in[3];
    float* out = (float*)d_out;

    npzd_kernel<<<(BB * WW) / TPB, TPB>>>(X_in, gf, gd, par, out);
}